// round 13
// baseline (speedup 1.0000x reference)
#include <cuda_runtime.h>
#include <cuda_fp16.h>
#include <math.h>

#define NN 100000
#define EE 1600000
#define NCAND 10000
#define GG 1000
#define ND 32
#define ED 8
#define LL 4

#define NTHR 256
#define MAXBLK 2048   // upper bound for safety clamp

__device__ float g_h[NN * ND];                        // 12.8 MB fp32
__device__ __align__(16) __half g_hs[NN * ED];        // 1.6 MB fp16
__device__ __align__(16) __half g_hd[NN * ED];        // 1.6 MB fp16
__device__ __align__(16) float  g_agg[NN * ED];       // 3.2 MB fp32
__device__ __align__(16) __half g_e[(size_t)EE * ED]; // 25.6 MB fp16
__device__ float    g_nl[NN];                         // per-node logits
__device__ unsigned g_mxu[GG];
__device__ float    g_sum[GG];

// ---------------- grid barrier (grid size = actual residency, from host) ----
__device__ unsigned g_cnt;
__device__ unsigned g_gen;

__device__ __forceinline__ void gbar() {
    __syncthreads();
    if (threadIdx.x == 0) {
        __threadfence();                       // release my block's writes
        unsigned gen = atomicAdd(&g_gen, 0u);  // read generation BEFORE arrival
        __threadfence();
        unsigned t = atomicAdd(&g_cnt, 1u);
        if (t == gridDim.x - 1) {
            *(volatile unsigned*)&g_cnt = 0u;
            __threadfence();
            atomicAdd(&g_gen, 1u);
        } else {
            while (*(volatile unsigned*)&g_gen == gen) { __nanosleep(64); }
        }
        __threadfence();                       // acquire (drop stale L1)
    }
    __syncthreads();
}

// ---------------- helpers ----------------
__device__ __forceinline__ unsigned enc_f(float f) {
    unsigned u = __float_as_uint(f);
    return (u & 0x80000000u) ? ~u : (u | 0x80000000u);
}
__device__ __forceinline__ float dec_f(unsigned k) {
    return __uint_as_float((k & 0x80000000u) ? (k ^ 0x80000000u) : ~k);
}

#define R_A (NN * ND)            // h
#define R_B (R_A + NN * 16)      // hs/hd layer 0
#define R_C (R_B + NN * ED)      // agg zero
#define R_D (R_C + GG)           // mx
#define R_E (R_D + GG)           // sum
#define TOT R_E

// ---------------- phases ----------------
__device__ __forceinline__ void init_phase(int gtid, int nt, float* SM,
        const float* x, const float* Wn, const float* bn,
        const float* Wel, const float* bel) {
    float* sC = SM;        // [2][16]
    float* sc0 = SM + 32;  // [16]
    int tid = threadIdx.x;
    if (tid < 48) {
        int r = tid >> 4, j = tid & 15;
        float acc = 0.f;
        if (r < 2) {
            for (int i = 0; i < ND; i++) {
                float w = (j < 8) ? Wel[i * ED + j] : Wel[(ND + i) * ED + (j - 8)];
                acc = fmaf(Wn[r * ND + i], w, acc);
            }
            sC[r * 16 + j] = acc;
        } else {
            for (int i = 0; i < ND; i++) {
                float w = (j < 8) ? Wel[i * ED + j] : Wel[(ND + i) * ED + (j - 8)];
                acc = fmaf(bn[i], w, acc);
            }
            sc0[j] = acc + ((j < 8) ? bel[j] : 0.f);
        }
    }
    __syncthreads();
    for (long t = gtid; t < TOT; t += nt) {
        if (t < R_A) {
            int n = (int)(t >> 5), c = (int)(t & 31);
            g_h[t] = fmaf(x[2 * n], Wn[c], fmaf(x[2 * n + 1], Wn[ND + c], bn[c]));
        } else if (t < R_B) {
            long u = t - R_A;
            int n = (int)(u >> 4), j = (int)(u & 15);
            float v = fmaf(x[2 * n], sC[j], fmaf(x[2 * n + 1], sC[16 + j], sc0[j]));
            if (j < 8) g_hs[n * ED + j] = __float2half(v);
            else       g_hd[n * ED + (j - 8)] = __float2half(v);
        } else if (t < R_C) {
            g_agg[t - R_B] = 0.f;
        } else if (t < R_D) {
            g_mxu[t - R_C] = 0u;          // == enc(-inf) lower bound
        } else {
            g_sum[t - R_D] = 0.f;
        }
    }
}

// Edge phase: thread per edge; l==0 computes e in-register (rank-1).
__device__ __forceinline__ void edge_phase(int gtid, int nt, float* SM,
        const int* ei, const float* ea, const float* Wel,
        const float* Wei, const float* bei, int l) {
    float* sW = SM;         // 64
    float* sWei = SM + 64;  // 8
    float* sbei = SM + 72;  // 8
    if (threadIdx.x < 64)
        sW[threadIdx.x] = Wel[l * (2 * ND + ED) * ED + 2 * ND * ED + threadIdx.x];
    if (l == 0 && threadIdx.x >= 64 && threadIdx.x < 80) {
        int j = threadIdx.x - 64;
        if (j < 8) sWei[j] = Wei[j];
        else       sbei[j - 8] = bei[j - 8];
    }
    __syncthreads();
    for (int e = gtid; e < EE; e += nt) {
        int src = ei[e], dst = ei[EE + e];
        float ein[8];
        if (l == 0) {
            float v = ea[e];
#pragma unroll
            for (int j = 0; j < 8; j++) ein[j] = fmaf(v, sWei[j], sbei[j]);
        } else {
            uint4 ev = *(const uint4*)&g_e[(size_t)e * ED];
            const __half2* eh = (const __half2*)&ev;
#pragma unroll
            for (int k = 0; k < 4; k++) {
                float2 ef = __half22float2(eh[k]);
                ein[2 * k] = ef.x;
                ein[2 * k + 1] = ef.y;
            }
        }
        uint4 sv = *(const uint4*)&g_hs[(size_t)src * ED];
        uint4 dv = *(const uint4*)&g_hd[(size_t)dst * ED];
        const __half2* sh = (const __half2*)&sv;
        const __half2* dh = (const __half2*)&dv;
        float base[8];
#pragma unroll
        for (int k = 0; k < 4; k++) {
            float2 sf = __half22float2(sh[k]);
            float2 df = __half22float2(dh[k]);
            base[2 * k] = sf.x + df.x;
            base[2 * k + 1] = sf.y + df.y;
        }
        float ne[8];
#pragma unroll
        for (int j = 0; j < 8; j++) {
            float acc = base[j];
#pragma unroll
            for (int i = 0; i < 8; i++) acc = fmaf(ein[i], sW[i * ED + j], acc);
            ne[j] = fmaxf(acc, 0.f);
        }
        float* ap = &g_agg[(size_t)dst * ED];
        asm volatile("red.global.add.v4.f32 [%0], {%1,%2,%3,%4};"
                     :: "l"(ap), "f"(ne[0]), "f"(ne[1]), "f"(ne[2]), "f"(ne[3]) : "memory");
        asm volatile("red.global.add.v4.f32 [%0], {%1,%2,%3,%4};"
                     :: "l"(ap + 4), "f"(ne[4]), "f"(ne[5]), "f"(ne[6]), "f"(ne[7]) : "memory");
        if (l < LL - 1) {
            __half2 o[4];
#pragma unroll
            for (int k = 0; k < 4; k++)
                o[k] = __floats2half2_rn(ein[2 * k] + ne[2 * k],
                                         ein[2 * k + 1] + ne[2 * k + 1]);
            *(uint4*)&g_e[(size_t)e * ED] = *(uint4*)o;
        }
    }
}

__device__ __forceinline__ void node_phase(int gtid, int nwarp, float* SM,
        const float* Wnl, const float* bnl, const float* Wel, const float* bel,
        const float* Wout, const float* bout, int l) {
    float* sW = SM;           // 1280
    float* sb = SM + 1280;    // 32
    float* sE = SM + 1312;    // 512 (32x16)
    float* sbe = SM + 1824;   // 8
    float* sWo = SM + 1832;   // 32
    float* sbo = SM + 1864;   // 1
    const int last = (l == LL - 1);
    for (int i = threadIdx.x; i < (ND + ED) * ND; i += NTHR)
        sW[i] = Wnl[l * (ND + ED) * ND + i];
    if (threadIdx.x < ND) sb[threadIdx.x] = bnl[l * ND + threadIdx.x];
    if (!last) {
        const float* W = Wel + (l + 1) * (2 * ND + ED) * ED;
        for (int i = threadIdx.x; i < ND * 16; i += NTHR) {
            int r = i >> 4, j = i & 15;
            sE[i] = (j < 8) ? W[r * ED + j] : W[(ND + r) * ED + (j - 8)];
        }
        if (threadIdx.x < 8) sbe[threadIdx.x] = bel[(l + 1) * ED + threadIdx.x];
    } else {
        if (threadIdx.x < ND) sWo[threadIdx.x] = Wout[threadIdx.x];
        if (threadIdx.x == 0) sbo[0] = bout[0];
    }
    __syncthreads();
    int lane = threadIdx.x & 31;
    for (int n = gtid >> 5; n < NN; n += nwarp) {
        float hv = g_h[n * ND + lane];
        float av = (lane < ED) ? g_agg[n * ED + lane] : 0.f;
        float r = sb[lane];
#pragma unroll
        for (int i = 0; i < ND; i++)
            r = fmaf(__shfl_sync(0xffffffffu, hv, i), sW[i * ND + lane], r);
#pragma unroll
        for (int i = 0; i < ED; i++)
            r = fmaf(__shfl_sync(0xffffffffu, av, i), sW[(ND + i) * ND + lane], r);
        float hnew = hv + fmaxf(r, 0.f);
        if (!last) {
            g_h[n * ND + lane] = hnew;
            float acc = (lane < 8) ? sbe[lane] : 0.f;
            int jj = lane & 15;
#pragma unroll
            for (int i = 0; i < ND; i++)
                acc = fmaf(__shfl_sync(0xffffffffu, hnew, i), sE[i * 16 + jj], acc);
            if (lane < 8) {
                g_hs[n * ED + lane] = __float2half(acc);
                g_agg[n * ED + lane] = 0.f;
            } else if (lane < 16) {
                g_hd[n * ED + (lane - 8)] = __float2half(acc);
            }
        } else {
            float p = hnew * sWo[lane];
#pragma unroll
            for (int s = 16; s > 0; s >>= 1)
                p += __shfl_xor_sync(0xffffffffu, p, s);
            if (lane == 0) g_nl[n] = p + sbo[0];
        }
    }
}

// ---------------- mega kernel ----------------
__global__ void __launch_bounds__(NTHR, 7)
k_mega(const float* __restrict__ x,
       const float* __restrict__ ea,
       const float* __restrict__ Wn_in, const float* __restrict__ bn_in,
       const float* __restrict__ We_in, const float* __restrict__ be_in,
       const float* __restrict__ We_l,  const float* __restrict__ be_l,
       const float* __restrict__ Wn_l,  const float* __restrict__ bn_l,
       const float* __restrict__ Wout,  const float* __restrict__ bout,
       const int* __restrict__ ei,      const int* __restrict__ batch,
       const int* __restrict__ cand,    float* __restrict__ out) {
    __shared__ float SM[2048];
    const int nt = gridDim.x * NTHR;
    const int nwarp = nt >> 5;
    int gtid = blockIdx.x * NTHR + threadIdx.x;

    init_phase(gtid, nt, SM, x, Wn_in, bn_in, We_l, be_l);
    gbar();
    for (int l = 0; l < LL; l++) {
        edge_phase(gtid, nt, SM, ei, ea, We_l, We_in, be_in, l);
        gbar();
        node_phase(gtid, nwarp, SM, Wn_l, bn_l, We_l, be_l, Wout, bout, l);
        gbar();
    }
    // readout phase A: per-graph max
    for (int c = gtid; c < NCAND; c += nt) {
        int n = cand[c];
        atomicMax(&g_mxu[batch[n]], enc_f(g_nl[n]));
    }
    gbar();
    // phase B: sum of exp
    for (int c = gtid; c < NCAND; c += nt) {
        int n = cand[c];
        int s = batch[n];
        atomicAdd(&g_sum[s], expf(g_nl[n] - dec_f(g_mxu[s])));
    }
    gbar();
    // phase C: write output
    for (int c = gtid; c < NCAND; c += nt) {
        int n = cand[c];
        int s = batch[n];
        out[c] = g_nl[n] - dec_f(g_mxu[s]) - logf(g_sum[s]);
    }
}

extern "C" void kernel_launch(void* const* d_in, const int* in_sizes, int n_in,
                              void* d_out, int out_size) {
    const float* x         = (const float*)d_in[0];
    const float* edge_attr = (const float*)d_in[1];
    const float* Wn_in     = (const float*)d_in[2];
    const float* bn_in     = (const float*)d_in[3];
    const float* We_in     = (const float*)d_in[4];
    const float* be_in     = (const float*)d_in[5];
    const float* We_l      = (const float*)d_in[6];
    const float* be_l      = (const float*)d_in[7];
    const float* Wn_l      = (const float*)d_in[8];
    const float* bn_l      = (const float*)d_in[9];
    const float* Wout      = (const float*)d_in[10];
    const float* bout      = (const float*)d_in[11];
    const int* edge_index  = (const int*)d_in[12];
    const int* batch       = (const int*)d_in[13];
    const int* cand        = (const int*)d_in[14];
    float* out = (float*)d_out;

    // Provable co-residency: grid = (measured blocks/SM) x (SM count).
    // Host-side queries only — graph-capture legal, deterministic.
    int dev = 0;
    cudaGetDevice(&dev);
    int nsm = 0;
    cudaDeviceGetAttribute(&nsm, cudaDevAttrMultiProcessorCount, dev);
    int bpsm = 0;
    cudaOccupancyMaxActiveBlocksPerMultiprocessor(&bpsm, k_mega, NTHR, 0);
    if (nsm <= 0) nsm = 148;
    if (bpsm <= 0) bpsm = 1;
    int nblk = nsm * bpsm;
    if (nblk > MAXBLK) nblk = MAXBLK;

    k_mega<<<nblk, NTHR>>>(x, edge_attr, Wn_in, bn_in, We_in, be_in,
                           We_l, be_l, Wn_l, bn_l, Wout, bout,
                           edge_index, batch, cand, out);
}

// round 14
// speedup vs baseline: 1.6674x; 1.6674x over previous
#include <cuda_runtime.h>
#include <cuda_fp16.h>
#include <math.h>

#define NN 100000
#define EE 1600000
#define NCAND 10000
#define GG 1000
#define ND 32
#define ED 8
#define LL 4

#define NBLK 444
#define NTHR 512
#define NT (NBLK * NTHR)
#define NWARP (NBLK * (NTHR / 32))

__device__ float g_h[NN * ND];                        // 12.8 MB fp32
__device__ __align__(16) __half g_hs[NN * ED];        // 1.6 MB fp16
__device__ __align__(16) __half g_hd[NN * ED];        // 1.6 MB fp16
__device__ __align__(16) float  g_agg[NN * ED];       // 3.2 MB fp32
__device__ __align__(16) __half g_e[(size_t)EE * ED]; // 25.6 MB fp16
__device__ float    g_nl[NN];                         // per-node logits
__device__ unsigned g_mxu[GG];
__device__ float    g_sum[GG];

// ---------------- grid barrier (pure spin — nanosleep measured to cost
// ~20us/barrier in wakeup tail; R6 pure-spin config is the proven one) -------
__device__ unsigned g_cnt;
__device__ unsigned g_gen;

__device__ __forceinline__ void gbar() {
    __syncthreads();
    if (threadIdx.x == 0) {
        __threadfence();                       // release my block's writes
        unsigned gen = atomicAdd(&g_gen, 0u);  // read generation BEFORE arrival
        __threadfence();
        unsigned t = atomicAdd(&g_cnt, 1u);
        if (t == NBLK - 1) {
            *(volatile unsigned*)&g_cnt = 0u;
            __threadfence();
            atomicAdd(&g_gen, 1u);
        } else {
            while (*(volatile unsigned*)&g_gen == gen) { }
        }
        __threadfence();                       // acquire (drop stale L1)
    }
    __syncthreads();
}

// ---------------- helpers ----------------
__device__ __forceinline__ unsigned enc_f(float f) {
    unsigned u = __float_as_uint(f);
    return (u & 0x80000000u) ? ~u : (u | 0x80000000u);
}
__device__ __forceinline__ float dec_f(unsigned k) {
    return __uint_as_float((k & 0x80000000u) ? (k ^ 0x80000000u) : ~k);
}

#define R_A (NN * ND)            // h
#define R_B (R_A + NN * 16)      // hs/hd layer 0
#define R_C (R_B + NN * ED)      // agg zero
#define R_D (R_C + GG)           // mx
#define R_E (R_D + GG)           // sum
#define TOT R_E

// ---------------- phases ----------------
__device__ __forceinline__ void init_phase(int gtid, float* SM,
        const float* x, const float* Wn, const float* bn,
        const float* Wel, const float* bel) {
    float* sC = SM;        // [2][16]
    float* sc0 = SM + 32;  // [16]
    int tid = threadIdx.x;
    if (tid < 48) {
        int r = tid >> 4, j = tid & 15;
        float acc = 0.f;
        if (r < 2) {
            for (int i = 0; i < ND; i++) {
                float w = (j < 8) ? Wel[i * ED + j] : Wel[(ND + i) * ED + (j - 8)];
                acc = fmaf(Wn[r * ND + i], w, acc);
            }
            sC[r * 16 + j] = acc;
        } else {
            for (int i = 0; i < ND; i++) {
                float w = (j < 8) ? Wel[i * ED + j] : Wel[(ND + i) * ED + (j - 8)];
                acc = fmaf(bn[i], w, acc);
            }
            sc0[j] = acc + ((j < 8) ? bel[j] : 0.f);
        }
    }
    __syncthreads();
    for (long t = gtid; t < TOT; t += NT) {
        if (t < R_A) {
            int n = (int)(t >> 5), c = (int)(t & 31);
            g_h[t] = fmaf(x[2 * n], Wn[c], fmaf(x[2 * n + 1], Wn[ND + c], bn[c]));
        } else if (t < R_B) {
            long u = t - R_A;
            int n = (int)(u >> 4), j = (int)(u & 15);
            float v = fmaf(x[2 * n], sC[j], fmaf(x[2 * n + 1], sC[16 + j], sc0[j]));
            if (j < 8) g_hs[n * ED + j] = __float2half(v);
            else       g_hd[n * ED + (j - 8)] = __float2half(v);
        } else if (t < R_C) {
            g_agg[t - R_B] = 0.f;
        } else if (t < R_D) {
            g_mxu[t - R_C] = 0u;          // == enc(-inf) lower bound
        } else {
            g_sum[t - R_D] = 0.f;
        }
    }
}

// Edge phase: thread per edge; l==0 computes e in-register (rank-1).
// MLP inner product uses float4 weight-row loads: 16 LDS.128 per edge
// instead of 64 scalar LDS (red-asm memory clobber defeats hoisting).
__device__ __forceinline__ void edge_phase(int gtid, float* SM,
        const int* ei, const float* ea, const float* Wel,
        const float* Wei, const float* bei, int l) {
    float* sW = SM;         // 64 (16B aligned)
    float* sWei = SM + 64;  // 8
    float* sbei = SM + 72;  // 8
    if (threadIdx.x < 64)
        sW[threadIdx.x] = Wel[l * (2 * ND + ED) * ED + 2 * ND * ED + threadIdx.x];
    if (l == 0 && threadIdx.x >= 64 && threadIdx.x < 80) {
        int j = threadIdx.x - 64;
        if (j < 8) sWei[j] = Wei[j];
        else       sbei[j - 8] = bei[j - 8];
    }
    __syncthreads();
    for (int e = gtid; e < EE; e += NT) {
        int src = ei[e], dst = ei[EE + e];
        float ein[8];
        if (l == 0) {
            float v = ea[e];
#pragma unroll
            for (int j = 0; j < 8; j++) ein[j] = fmaf(v, sWei[j], sbei[j]);
        } else {
            uint4 ev = *(const uint4*)&g_e[(size_t)e * ED];
            const __half2* eh = (const __half2*)&ev;
#pragma unroll
            for (int k = 0; k < 4; k++) {
                float2 ef = __half22float2(eh[k]);
                ein[2 * k] = ef.x;
                ein[2 * k + 1] = ef.y;
            }
        }
        uint4 sv = *(const uint4*)&g_hs[(size_t)src * ED];
        uint4 dv = *(const uint4*)&g_hd[(size_t)dst * ED];
        const __half2* sh = (const __half2*)&sv;
        const __half2* dh = (const __half2*)&dv;
        float ne[8];
#pragma unroll
        for (int k = 0; k < 4; k++) {
            float2 sf = __half22float2(sh[k]);
            float2 df = __half22float2(dh[k]);
            ne[2 * k] = sf.x + df.x;
            ne[2 * k + 1] = sf.y + df.y;
        }
#pragma unroll
        for (int i = 0; i < 8; i++) {
            float4 w0 = *(const float4*)&sW[i * 8];
            float4 w1 = *(const float4*)&sW[i * 8 + 4];
            float ev2 = ein[i];
            ne[0] = fmaf(ev2, w0.x, ne[0]);
            ne[1] = fmaf(ev2, w0.y, ne[1]);
            ne[2] = fmaf(ev2, w0.z, ne[2]);
            ne[3] = fmaf(ev2, w0.w, ne[3]);
            ne[4] = fmaf(ev2, w1.x, ne[4]);
            ne[5] = fmaf(ev2, w1.y, ne[5]);
            ne[6] = fmaf(ev2, w1.z, ne[6]);
            ne[7] = fmaf(ev2, w1.w, ne[7]);
        }
#pragma unroll
        for (int j = 0; j < 8; j++) ne[j] = fmaxf(ne[j], 0.f);
        float* ap = &g_agg[(size_t)dst * ED];
        asm volatile("red.global.add.v4.f32 [%0], {%1,%2,%3,%4};"
                     :: "l"(ap), "f"(ne[0]), "f"(ne[1]), "f"(ne[2]), "f"(ne[3]) : "memory");
        asm volatile("red.global.add.v4.f32 [%0], {%1,%2,%3,%4};"
                     :: "l"(ap + 4), "f"(ne[4]), "f"(ne[5]), "f"(ne[6]), "f"(ne[7]) : "memory");
        if (l < LL - 1) {
            __half2 o[4];
#pragma unroll
            for (int k = 0; k < 4; k++)
                o[k] = __floats2half2_rn(ein[2 * k] + ne[2 * k],
                                         ein[2 * k + 1] + ne[2 * k + 1]);
            *(uint4*)&g_e[(size_t)e * ED] = *(uint4*)o;
        }
    }
}

__device__ __forceinline__ void node_phase(int gtid, float* SM,
        const float* Wnl, const float* bnl, const float* Wel, const float* bel,
        const float* Wout, const float* bout, int l) {
    float* sW = SM;           // 1280
    float* sb = SM + 1280;    // 32
    float* sE = SM + 1312;    // 512 (32x16)
    float* sbe = SM + 1824;   // 8
    float* sWo = SM + 1832;   // 32
    float* sbo = SM + 1864;   // 1
    const int last = (l == LL - 1);
    for (int i = threadIdx.x; i < (ND + ED) * ND; i += NTHR)
        sW[i] = Wnl[l * (ND + ED) * ND + i];
    if (threadIdx.x < ND) sb[threadIdx.x] = bnl[l * ND + threadIdx.x];
    if (!last) {
        const float* W = Wel + (l + 1) * (2 * ND + ED) * ED;
        for (int i = threadIdx.x; i < ND * 16; i += NTHR) {
            int r = i >> 4, j = i & 15;
            sE[i] = (j < 8) ? W[r * ED + j] : W[(ND + r) * ED + (j - 8)];
        }
        if (threadIdx.x < 8) sbe[threadIdx.x] = bel[(l + 1) * ED + threadIdx.x];
    } else {
        if (threadIdx.x < ND) sWo[threadIdx.x] = Wout[threadIdx.x];
        if (threadIdx.x == 0) sbo[0] = bout[0];
    }
    __syncthreads();
    int lane = threadIdx.x & 31;
    for (int n = gtid >> 5; n < NN; n += NWARP) {
        float hv = g_h[n * ND + lane];
        float av = (lane < ED) ? g_agg[n * ED + lane] : 0.f;
        float r = sb[lane];
#pragma unroll
        for (int i = 0; i < ND; i++)
            r = fmaf(__shfl_sync(0xffffffffu, hv, i), sW[i * ND + lane], r);
#pragma unroll
        for (int i = 0; i < ED; i++)
            r = fmaf(__shfl_sync(0xffffffffu, av, i), sW[(ND + i) * ND + lane], r);
        float hnew = hv + fmaxf(r, 0.f);
        if (!last) {
            g_h[n * ND + lane] = hnew;
            float acc = (lane < 8) ? sbe[lane] : 0.f;
            int jj = lane & 15;
#pragma unroll
            for (int i = 0; i < ND; i++)
                acc = fmaf(__shfl_sync(0xffffffffu, hnew, i), sE[i * 16 + jj], acc);
            if (lane < 8) {
                g_hs[n * ED + lane] = __float2half(acc);
                g_agg[n * ED + lane] = 0.f;
            } else if (lane < 16) {
                g_hd[n * ED + (lane - 8)] = __float2half(acc);
            }
        } else {
            float p = hnew * sWo[lane];
#pragma unroll
            for (int s = 16; s > 0; s >>= 1)
                p += __shfl_xor_sync(0xffffffffu, p, s);
            if (lane == 0) g_nl[n] = p + sbo[0];
        }
    }
}

// ---------------- mega kernel ----------------
__global__ void __launch_bounds__(NTHR, 3)
k_mega(const float* __restrict__ x,
       const float* __restrict__ ea,
       const float* __restrict__ Wn_in, const float* __restrict__ bn_in,
       const float* __restrict__ We_in, const float* __restrict__ be_in,
       const float* __restrict__ We_l,  const float* __restrict__ be_l,
       const float* __restrict__ Wn_l,  const float* __restrict__ bn_l,
       const float* __restrict__ Wout,  const float* __restrict__ bout,
       const int* __restrict__ ei,      const int* __restrict__ batch,
       const int* __restrict__ cand,    float* __restrict__ out) {
    __shared__ __align__(16) float SM[2048];
    int gtid = blockIdx.x * NTHR + threadIdx.x;

    init_phase(gtid, SM, x, Wn_in, bn_in, We_l, be_l);
    gbar();
    for (int l = 0; l < LL; l++) {
        edge_phase(gtid, SM, ei, ea, We_l, We_in, be_in, l);
        gbar();
        node_phase(gtid, SM, Wn_l, bn_l, We_l, be_l, Wout, bout, l);
        gbar();
    }
    // readout phase A: per-graph max
    for (int c = gtid; c < NCAND; c += NT) {
        int n = cand[c];
        atomicMax(&g_mxu[batch[n]], enc_f(g_nl[n]));
    }
    gbar();
    // phase B: sum of exp
    for (int c = gtid; c < NCAND; c += NT) {
        int n = cand[c];
        int s = batch[n];
        atomicAdd(&g_sum[s], expf(g_nl[n] - dec_f(g_mxu[s])));
    }
    gbar();
    // phase C: write output
    for (int c = gtid; c < NCAND; c += NT) {
        int n = cand[c];
        int s = batch[n];
        out[c] = g_nl[n] - dec_f(g_mxu[s]) - logf(g_sum[s]);
    }
}

extern "C" void kernel_launch(void* const* d_in, const int* in_sizes, int n_in,
                              void* d_out, int out_size) {
    const float* x         = (const float*)d_in[0];
    const float* edge_attr = (const float*)d_in[1];
    const float* Wn_in     = (const float*)d_in[2];
    const float* bn_in     = (const float*)d_in[3];
    const float* We_in     = (const float*)d_in[4];
    const float* be_in     = (const float*)d_in[5];
    const float* We_l      = (const float*)d_in[6];
    const float* be_l      = (const float*)d_in[7];
    const float* Wn_l      = (const float*)d_in[8];
    const float* bn_l      = (const float*)d_in[9];
    const float* Wout      = (const float*)d_in[10];
    const float* bout      = (const float*)d_in[11];
    const int* edge_index  = (const int*)d_in[12];
    const int* batch       = (const int*)d_in[13];
    const int* cand        = (const int*)d_in[14];
    float* out = (float*)d_out;

    k_mega<<<NBLK, NTHR>>>(x, edge_attr, Wn_in, bn_in, We_in, be_in,
                           We_l, be_l, Wn_l, bn_l, Wout, bout,
                           edge_index, batch, cand, out);
}